// round 14
// baseline (speedup 1.0000x reference)
#include <cuda_runtime.h>
#include <cuda_fp16.h>
#include <cstdint>

#define NU 200000
#define NM 80000
#define NN 280000            // real nodes
#define NP 280064            // padded to 2188*128
#define H  64
#define EMAX 1250000
#define NB 274               // ceil(NP/1024)

// ---------------- scratch (device globals; no allocation allowed) ----------
__device__ float  g_XM[(size_t)(NP - NU) * H]; // movie feats fp32 (pads stay 0)
__device__ __half g_XB[(size_t)NP * H];        // fp16 shadow (gather + score src)
__device__ float  g_X1[(size_t)NP * H];        // layer-1 output (fp32)
__device__ float  g_MEAN[(size_t)NP * H];      // aggregated mean (fp32)
__device__ int    g_CNT[NP];
__device__ int    g_OFF[NP];
__device__ int    g_CUR[NP];
__device__ float  g_INV[NP];
__device__ int    g_BIN[EMAX];
__device__ int    g_BS[NB];
__device__ int    g_flag32[1];                 // 1 => int32 indices, 0 => int64

// ---------------- index dtype detection ------------------------------------
__global__ void k_zero_flag() { g_flag32[0] = 0; }

__global__ void k_detect(const long long* __restrict__ ei, int ncheck) {
    int i = blockIdx.x * blockDim.x + threadIdx.x;
    if (i < ncheck) {
        long long v = ei[i];
        if (v < 0 || v >= (long long)NN) atomicOr(g_flag32, 1);
    }
}

__device__ __forceinline__ int get_idx(const void* ei, int pos, int f32) {
    if (f32) return ((const int*)ei)[pos];
    return (int)((const long long*)ei)[pos];
}

// ---------------- fp16 shadow of user features ------------------------------
__global__ void k_conv_user(const float2* __restrict__ XU) {
    int i = blockIdx.x * blockDim.x + threadIdx.x;   // half2 units
    if (i >= NU * H / 2) return;
    float2 v = __ldg(&XU[i]);
    ((__half2*)g_XB)[i] = __floats2half2_rn(v.x, v.y);
}

// ---------------- movie node init (W in registers, 32 movies/block) ---------
__global__ void __launch_bounds__(512)
k_init_movie(const float* __restrict__ movie_x,
             const float* __restrict__ lin_W,
             const float* __restrict__ lin_b,
             const float* __restrict__ movie_emb) {
    __shared__ float Wt[20][68];          // transposed, padded
    __shared__ float bsh[64];
    __shared__ float mx[32][20];

    int tid = threadIdx.x;
    int m0  = blockIdx.x * 32;            // first movie of this block

    for (int i = tid; i < 64 * 20; i += 512) {
        int j = i / 20, k = i % 20;       // lin_W[j][k]
        Wt[k][j] = __ldg(&lin_W[i]);
    }
    if (tid < 64) bsh[tid] = __ldg(&lin_b[tid]);
    for (int i = tid; i < 32 * 20; i += 512)
        mx[i / 20][i % 20] = __ldg(&movie_x[m0 * 20 + i]);
    __syncthreads();

    int j = tid & 63, mgrp = tid >> 6;    // column, movie-subgroup (0..7)

    float Wreg[20];
#pragma unroll
    for (int k = 0; k < 20; ++k) Wreg[k] = Wt[k][j];
    float b = bsh[j];

#pragma unroll
    for (int r = 0; r < 4; ++r) {
        int ml = r * 8 + mgrp;            // movie-local 0..31
        int m  = m0 + ml;
        float acc = b;
#pragma unroll
        for (int k = 0; k < 20; ++k)
            acc += mx[ml][k] * Wreg[k];
        acc += __ldg(&movie_emb[(size_t)m * H + j]);
        g_XM[(size_t)m * H + j] = acc;
        g_XB[(size_t)(NU + m) * H + j] = __float2half_rn(acc);
    }
}

// ---------------- CSR build --------------------------------------------------
__global__ void k_count(const void* __restrict__ ei, int E) {
    int e = blockIdx.x * blockDim.x + threadIdx.x;
    if (e >= E) return;
    int f = g_flag32[0];
    atomicAdd(&g_CNT[get_idx(ei, E + e, f)], 1);
}

__global__ void k_inv() {
    int i = blockIdx.x * blockDim.x + threadIdx.x;
    if (i < NP) g_INV[i] = 1.0f / fmaxf((float)g_CNT[i], 1.0f);
}

__global__ void k_blocksum() {
    __shared__ int sh[1024];
    int i = blockIdx.x * 1024 + threadIdx.x;
    sh[threadIdx.x] = (i < NP) ? g_CNT[i] : 0;
    __syncthreads();
    for (int s = 512; s > 0; s >>= 1) {
        if (threadIdx.x < s) sh[threadIdx.x] += sh[threadIdx.x + s];
        __syncthreads();
    }
    if (threadIdx.x == 0) g_BS[blockIdx.x] = sh[0];
}

__global__ void k_scan_bs() {
    __shared__ int a[512], b[512];
    int t = threadIdx.x;
    int v = (t < NB) ? g_BS[t] : 0;
    a[t] = v;
    __syncthreads();
    int *in = a, *out = b;
    for (int s = 1; s < 512; s <<= 1) {
        out[t] = in[t] + ((t >= s) ? in[t - s] : 0);
        __syncthreads();
        int* tmp = in; in = out; out = tmp;
    }
    if (t < NB) g_BS[t] = in[t] - v;   // exclusive
}

__global__ void k_scan_local() {
    __shared__ int a[1024], b[1024];
    int t = threadIdx.x;
    int i = blockIdx.x * 1024 + t;
    int v = (i < NP) ? g_CNT[i] : 0;
    a[t] = v;
    __syncthreads();
    int *in = a, *out = b;
    for (int s = 1; s < 1024; s <<= 1) {
        out[t] = in[t] + ((t >= s) ? in[t - s] : 0);
        __syncthreads();
        int* tmp = in; in = out; out = tmp;
    }
    if (i < NP) {
        int excl = in[t] - v + g_BS[blockIdx.x];
        g_OFF[i] = excl;
        g_CUR[i] = excl;
    }
}

__global__ void k_place(const void* __restrict__ ei, int E) {
    int e = blockIdx.x * blockDim.x + threadIdx.x;
    if (e >= E) return;
    int f = g_flag32[0];
    int src = get_idx(ei, e, f);
    int dst = get_idx(ei, E + e, f);
    int pos = atomicAdd(&g_CUR[dst], 1);
    g_BIN[pos] = src;
}

// ---------------- gather-mean from fp16 rows (MLP=4) -------------------------
// 8 threads per node; neighbor loop batched 4-wide: 4 independent index loads
// then 4 independent row loads in flight -> chain latency / 4.
__global__ void __launch_bounds__(256)
k_gather_mean(float4* __restrict__ MEAN) {
    int t = blockIdx.x * blockDim.x + threadIdx.x;
    int node = t >> 3, c = t & 7;
    if (node >= NP) return;
    int start = __ldg(&g_OFF[node]);
    int cnt   = __ldg(&g_CNT[node]);
    float inv = __ldg(&g_INV[node]);
    const uint4* XB4 = (const uint4*)g_XB;   // row = 8 uint4
    float s0 = 0.f, s1 = 0.f, s2 = 0.f, s3 = 0.f;
    float s4 = 0.f, s5 = 0.f, s6 = 0.f, s7 = 0.f;

    int i = 0;
    for (; i + 4 <= cnt; i += 4) {
        int a0 = __ldg(&g_BIN[start + i]);
        int a1 = __ldg(&g_BIN[start + i + 1]);
        int a2 = __ldg(&g_BIN[start + i + 2]);
        int a3 = __ldg(&g_BIN[start + i + 3]);
        uint4 r0 = __ldg(&XB4[(size_t)a0 * 8 + c]);
        uint4 r1 = __ldg(&XB4[(size_t)a1 * 8 + c]);
        uint4 r2 = __ldg(&XB4[(size_t)a2 * 8 + c]);
        uint4 r3 = __ldg(&XB4[(size_t)a3 * 8 + c]);
#define ACC(rr)                                                         \
        {                                                               \
            float2 p0 = __half22float2(*(__half2*)&rr.x);               \
            float2 p1 = __half22float2(*(__half2*)&rr.y);               \
            float2 p2 = __half22float2(*(__half2*)&rr.z);               \
            float2 p3 = __half22float2(*(__half2*)&rr.w);               \
            s0 += p0.x; s1 += p0.y; s2 += p1.x; s3 += p1.y;             \
            s4 += p2.x; s5 += p2.y; s6 += p3.x; s7 += p3.y;             \
        }
        ACC(r0) ACC(r1) ACC(r2) ACC(r3)
    }
    for (; i < cnt; ++i) {
        int a0 = __ldg(&g_BIN[start + i]);
        uint4 r0 = __ldg(&XB4[(size_t)a0 * 8 + c]);
        ACC(r0)
    }
#undef ACC

    float4 o0 = make_float4(s0 * inv, s1 * inv, s2 * inv, s3 * inv);
    float4 o1 = make_float4(s4 * inv, s5 * inv, s6 * inv, s7 * inv);
    MEAN[(size_t)node * 16 + c * 2]     = o0;
    MEAN[(size_t)node * 16 + c * 2 + 1] = o1;
}

// ---------------- tf32 helpers ----------------------------------------------
__device__ __forceinline__ uint32_t f2tf32(float x) {
    uint32_t r;
    asm("cvt.rna.tf32.f32 %0, %1;" : "=r"(r) : "f"(x));
    return r;
}

// ---------------- dense update via tensor cores ------------------------------
// out = [mean‖x](NP x 128) @ Wc(128 x 64) + b
// split=1: x rows from XU (row<NU) or g_XM. XBout!=0: emit fp16 shadow.
// Xout may be null (layer 2 needs only the fp16 shadow for scoring).
__global__ void __launch_bounds__(256)
k_dense_mma(const float* __restrict__ MEAN, const float* __restrict__ XU,
            int split,
            const float* __restrict__ Wl, const float* __restrict__ bvec,
            const float* __restrict__ Wr, float* __restrict__ Xout,
            __half* __restrict__ XBout, int do_relu) {
    __shared__ uint32_t Bs[128][72];
    __shared__ float bsh[64];

    int tid  = threadIdx.x;
    int base = blockIdx.x * 128;

    for (int i = tid; i < 128 * 64; i += 256) {
        int k = i & 127, j = i >> 7;
        float w = (k < 64) ? __ldg(&Wl[j * 64 + k]) : __ldg(&Wr[j * 64 + k - 64]);
        Bs[k][j] = f2tf32(w);
    }
    if (tid < 64) bsh[tid] = __ldg(&bvec[tid]);
    __syncthreads();

    int warp = tid >> 5, lane = tid & 31;
    int r = lane >> 2, c = lane & 3;
    int row0 = base + warp * 16 + r;        // rows row0, row0+8

    const float* xr0 = (split && row0 >= NU)
                     ? (g_XM + (size_t)(row0 - NU) * H)
                     : (XU + (size_t)row0 * H);
    const float* xr1 = (split && row0 + 8 >= NU)
                     ? (g_XM + (size_t)(row0 + 8 - NU) * H)
                     : (XU + (size_t)(row0 + 8) * H);

    float acc[8][4];
#pragma unroll
    for (int nf = 0; nf < 8; ++nf)
#pragma unroll
        for (int i = 0; i < 4; ++i) acc[nf][i] = 0.0f;

    const float* M0 = MEAN + (size_t)row0 * 64;
    const float* M1 = MEAN + (size_t)(row0 + 8) * 64;

#pragma unroll
    for (int ks = 0; ks < 16; ++ks) {
        int k0 = ks * 8;
        uint32_t a0, a1, a2, a3;
        if (ks < 8) {
            a0 = f2tf32(__ldg(&M0[k0 + c]));
            a1 = f2tf32(__ldg(&M1[k0 + c]));
            a2 = f2tf32(__ldg(&M0[k0 + c + 4]));
            a3 = f2tf32(__ldg(&M1[k0 + c + 4]));
        } else {
            int kk = k0 - 64;
            a0 = f2tf32(__ldg(&xr0[kk + c]));
            a1 = f2tf32(__ldg(&xr1[kk + c]));
            a2 = f2tf32(__ldg(&xr0[kk + c + 4]));
            a3 = f2tf32(__ldg(&xr1[kk + c + 4]));
        }
#pragma unroll
        for (int nf = 0; nf < 8; ++nf) {
            uint32_t b0 = Bs[k0 + c][8 * nf + r];
            uint32_t b1 = Bs[k0 + c + 4][8 * nf + r];
            asm volatile(
                "mma.sync.aligned.m16n8k8.row.col.f32.tf32.tf32.f32 "
                "{%0,%1,%2,%3}, {%4,%5,%6,%7}, {%8,%9}, {%0,%1,%2,%3};"
                : "+f"(acc[nf][0]), "+f"(acc[nf][1]),
                  "+f"(acc[nf][2]), "+f"(acc[nf][3])
                : "r"(a0), "r"(a1), "r"(a2), "r"(a3), "r"(b0), "r"(b1));
        }
    }

#pragma unroll
    for (int nf = 0; nf < 8; ++nf) {
        int col = 8 * nf + 2 * c;
        float o0 = acc[nf][0] + bsh[col];
        float o1 = acc[nf][1] + bsh[col + 1];
        float o2 = acc[nf][2] + bsh[col];
        float o3 = acc[nf][3] + bsh[col + 1];
        if (do_relu) {
            o0 = fmaxf(o0, 0.0f); o1 = fmaxf(o1, 0.0f);
            o2 = fmaxf(o2, 0.0f); o3 = fmaxf(o3, 0.0f);
        }
        if (Xout) {
            *(float2*)&Xout[(size_t)row0 * 64 + col]       = make_float2(o0, o1);
            *(float2*)&Xout[(size_t)(row0 + 8) * 64 + col] = make_float2(o2, o3);
        }
        if (XBout) {
            *(__half2*)&XBout[(size_t)row0 * 64 + col] =
                __floats2half2_rn(o0, o1);
            *(__half2*)&XBout[(size_t)(row0 + 8) * 64 + col] =
                __floats2half2_rn(o2, o3);
        }
    }
}

// ---------------- scoring (fp16 features) ------------------------------------
// out[e] = dot(XB[u[e]], XB[NU+m[e]]); 8 threads/edge (16B fp16 chunks)
__global__ void k_score(const void* __restrict__ eli,
                        float* __restrict__ out, int EL) {
    int t = blockIdx.x * blockDim.x + threadIdx.x;
    if (t >= EL * 8) return;
    int e = t >> 3, c = t & 7;
    int f = g_flag32[0];
    int u = get_idx(eli, e, f);
    int m = get_idx(eli, EL + e, f);
    uint4 ra = __ldg((const uint4*)(g_XB + (size_t)u * H) + c);
    uint4 rb = __ldg((const uint4*)(g_XB + (size_t)(NU + m) * H) + c);
    float2 a0 = __half22float2(*(__half2*)&ra.x);
    float2 a1 = __half22float2(*(__half2*)&ra.y);
    float2 a2 = __half22float2(*(__half2*)&ra.z);
    float2 a3 = __half22float2(*(__half2*)&ra.w);
    float2 b0 = __half22float2(*(__half2*)&rb.x);
    float2 b1 = __half22float2(*(__half2*)&rb.y);
    float2 b2 = __half22float2(*(__half2*)&rb.z);
    float2 b3 = __half22float2(*(__half2*)&rb.w);
    float p = a0.x * b0.x + a0.y * b0.y + a1.x * b1.x + a1.y * b1.y
            + a2.x * b2.x + a2.y * b2.y + a3.x * b3.x + a3.y * b3.y;
    p += __shfl_xor_sync(0xffffffffu, p, 4);
    p += __shfl_xor_sync(0xffffffffu, p, 2);
    p += __shfl_xor_sync(0xffffffffu, p, 1);
    if (c == 0) out[e] = p;
}

// ---------------- launch ----------------------------------------------------
extern "C" void kernel_launch(void* const* d_in, const int* in_sizes, int n_in,
                              void* d_out, int out_size) {
    const float* movie_x   = (const float*)d_in[0];
    const float* user_emb  = (const float*)d_in[1];
    const float* movie_emb = (const float*)d_in[2];
    const float* lin_W     = (const float*)d_in[3];
    const float* lin_b     = (const float*)d_in[4];
    const float* W1l = (const float*)d_in[5];
    const float* b1  = (const float*)d_in[6];
    const float* W1r = (const float*)d_in[7];
    const float* W2l = (const float*)d_in[8];
    const float* b2  = (const float*)d_in[9];
    const float* W2r = (const float*)d_in[10];
    const void*  ei  = d_in[11];
    const void*  eli = d_in[12];
    int E  = in_sizes[11] / 2;
    int EL = in_sizes[12] / 2;

    void *pX1, *pMEAN, *pCNT, *pXB;
    cudaGetSymbolAddress(&pX1, g_X1);
    cudaGetSymbolAddress(&pMEAN, g_MEAN);
    cudaGetSymbolAddress(&pCNT, g_CNT);
    cudaGetSymbolAddress(&pXB, g_XB);

    cudaMemsetAsync(pCNT, 0, (size_t)NP * sizeof(int), 0);

    k_zero_flag<<<1, 1>>>();
    k_detect<<<4, 256>>>((const long long*)ei, 1024);

    // fp16 shadow of layer-1 gather source + fp32 movie features
    k_conv_user<<<(NU * H / 2 + 255) / 256, 256>>>((const float2*)user_emb);
    k_init_movie<<<NM / 32, 512>>>(movie_x, lin_W, lin_b, movie_emb);

    // CSR build (shared by both layers)
    k_count<<<(E + 255) / 256, 256>>>(ei, E);
    k_inv<<<(NP + 255) / 256, 256>>>();
    k_blocksum<<<NB, 1024>>>();
    k_scan_bs<<<1, 512>>>();
    k_scan_local<<<NB, 1024>>>();
    k_place<<<(E + 255) / 256, 256>>>(ei, E);

    int ggrid = (NP * 8 + 255) / 256;

    // layer 1: gather from fp16 shadow; dense writes X1 + new fp16 shadow
    k_gather_mean<<<ggrid, 256>>>((float4*)pMEAN);
    k_dense_mma<<<NP / 128, 256>>>((const float*)pMEAN, user_emb, 1,
                                   W1l, b1, W1r, (float*)pX1, (__half*)pXB, 1);
    // layer 2: gather consumes XB(X1), then dense overwrites XB with X2 fp16
    k_gather_mean<<<ggrid, 256>>>((float4*)pMEAN);
    k_dense_mma<<<NP / 128, 256>>>((const float*)pMEAN, (const float*)pX1, 0,
                                   W2l, b2, W2r, (float*)0, (__half*)pXB, 0);

    // scoring from fp16 final features
    k_score<<<(EL * 8 + 255) / 256, 256>>>(eli, (float*)d_out, EL);
}

// round 17
// speedup vs baseline: 1.0934x; 1.0934x over previous
#include <cuda_runtime.h>
#include <cuda_fp16.h>
#include <cstdint>

#define NU 200000
#define NM 80000
#define NN 280000            // real nodes
#define NP 280064            // padded to 2188*128
#define H  64
#define EMAX 1250000
#define NB 274               // ceil(NP/1024)

// ---------------- scratch (device globals; no allocation allowed) ----------
__device__ __half g_XB[(size_t)NP * H];   // fp16 features (all stages, in-place)
__device__ __half g_MH[(size_t)NP * H];   // fp16 aggregated mean
__device__ int    g_CNT[NP];
__device__ int    g_OFF[NP];
__device__ int    g_CUR[NP];
__device__ float  g_INV[NP];
__device__ int    g_BIN[EMAX];
__device__ int    g_BS[NB];
__device__ int    g_flag32[1] = {0};      // 1 => int32 indices, 0 => int64

// ---------------- index dtype detection ------------------------------------
__global__ void k_detect(const long long* __restrict__ ei, int ncheck) {
    int i = blockIdx.x * blockDim.x + threadIdx.x;
    if (i < ncheck) {
        long long v = ei[i];
        if (v < 0 || v >= (long long)NN) atomicOr(g_flag32, 1);
    }
}

__device__ __forceinline__ int get_idx(const void* ei, int pos, int f32) {
    if (f32) return ((const int*)ei)[pos];
    return (int)((const long long*)ei)[pos];
}

// ---------------- fp16 shadow of user features ------------------------------
__global__ void k_conv_user(const float2* __restrict__ XU) {
    int i = blockIdx.x * blockDim.x + threadIdx.x;   // half2 units
    if (i >= NU * H / 2) return;
    float2 v = __ldg(&XU[i]);
    ((__half2*)g_XB)[i] = __floats2half2_rn(v.x, v.y);
}

// ---------------- movie node init (W in registers, 32 movies/block) ---------
__global__ void __launch_bounds__(512)
k_init_movie(const float* __restrict__ movie_x,
             const float* __restrict__ lin_W,
             const float* __restrict__ lin_b,
             const float* __restrict__ movie_emb) {
    __shared__ float Wt[20][68];          // transposed, padded
    __shared__ float bsh[64];
    __shared__ float mx[32][20];

    int tid = threadIdx.x;
    int m0  = blockIdx.x * 32;            // first movie of this block

    for (int i = tid; i < 64 * 20; i += 512) {
        int j = i / 20, k = i % 20;       // lin_W[j][k]
        Wt[k][j] = __ldg(&lin_W[i]);
    }
    if (tid < 64) bsh[tid] = __ldg(&lin_b[tid]);
    for (int i = tid; i < 32 * 20; i += 512)
        mx[i / 20][i % 20] = __ldg(&movie_x[m0 * 20 + i]);
    __syncthreads();

    int j = tid & 63, mgrp = tid >> 6;    // column, movie-subgroup (0..7)

    float Wreg[20];
#pragma unroll
    for (int k = 0; k < 20; ++k) Wreg[k] = Wt[k][j];
    float b = bsh[j];

#pragma unroll
    for (int r = 0; r < 4; ++r) {
        int ml = r * 8 + mgrp;            // movie-local 0..31
        int m  = m0 + ml;
        float acc = b;
#pragma unroll
        for (int k = 0; k < 20; ++k)
            acc += mx[ml][k] * Wreg[k];
        acc += __ldg(&movie_emb[(size_t)m * H + j]);
        g_XB[(size_t)(NU + m) * H + j] = __float2half_rn(acc);
    }
}

// ---------------- CSR build --------------------------------------------------
__global__ void k_count(const void* __restrict__ ei, int E) {
    int e = blockIdx.x * blockDim.x + threadIdx.x;
    if (e >= E) return;
    int f = g_flag32[0];
    atomicAdd(&g_CNT[get_idx(ei, E + e, f)], 1);
}

__global__ void k_inv() {
    int i = blockIdx.x * blockDim.x + threadIdx.x;
    if (i < NP) g_INV[i] = 1.0f / fmaxf((float)g_CNT[i], 1.0f);
}

__global__ void k_blocksum() {
    __shared__ int sh[1024];
    int i = blockIdx.x * 1024 + threadIdx.x;
    sh[threadIdx.x] = (i < NP) ? g_CNT[i] : 0;
    __syncthreads();
    for (int s = 512; s > 0; s >>= 1) {
        if (threadIdx.x < s) sh[threadIdx.x] += sh[threadIdx.x + s];
        __syncthreads();
    }
    if (threadIdx.x == 0) g_BS[blockIdx.x] = sh[0];
}

__global__ void k_scan_bs() {
    __shared__ int a[512], b[512];
    int t = threadIdx.x;
    int v = (t < NB) ? g_BS[t] : 0;
    a[t] = v;
    __syncthreads();
    int *in = a, *out = b;
    for (int s = 1; s < 512; s <<= 1) {
        out[t] = in[t] + ((t >= s) ? in[t - s] : 0);
        __syncthreads();
        int* tmp = in; in = out; out = tmp;
    }
    if (t < NB) g_BS[t] = in[t] - v;   // exclusive
}

__global__ void k_scan_local() {
    __shared__ int a[1024], b[1024];
    int t = threadIdx.x;
    int i = blockIdx.x * 1024 + t;
    int v = (i < NP) ? g_CNT[i] : 0;
    a[t] = v;
    __syncthreads();
    int *in = a, *out = b;
    for (int s = 1; s < 1024; s <<= 1) {
        out[t] = in[t] + ((t >= s) ? in[t - s] : 0);
        __syncthreads();
        int* tmp = in; in = out; out = tmp;
    }
    if (i < NP) {
        int excl = in[t] - v + g_BS[blockIdx.x];
        g_OFF[i] = excl;
        g_CUR[i] = excl;
    }
}

__global__ void k_place(const void* __restrict__ ei, int E) {
    int e = blockIdx.x * blockDim.x + threadIdx.x;
    if (e >= E) return;
    int f = g_flag32[0];
    int src = get_idx(ei, e, f);
    int dst = get_idx(ei, E + e, f);
    int pos = atomicAdd(&g_CUR[dst], 1);
    g_BIN[pos] = src;
}

// ---------------- gather-mean: fp16 rows -> fp16 mean ------------------------
// 8 threads per node; each owns 16B (8 halves) of the 128B row.
__global__ void __launch_bounds__(256)
k_gather_mean() {
    int t = blockIdx.x * blockDim.x + threadIdx.x;
    int node = t >> 3, c = t & 7;
    if (node >= NP) return;
    int start = __ldg(&g_OFF[node]);
    int cnt   = __ldg(&g_CNT[node]);
    float inv = __ldg(&g_INV[node]);
    const uint4* XB4 = (const uint4*)g_XB;   // row = 8 uint4
    float s0 = 0.f, s1 = 0.f, s2 = 0.f, s3 = 0.f;
    float s4 = 0.f, s5 = 0.f, s6 = 0.f, s7 = 0.f;
    for (int i = 0; i < cnt; ++i) {
        int src = __ldg(&g_BIN[start + i]);
        uint4 raw = __ldg(&XB4[(size_t)src * 8 + c]);
        float2 p0 = __half22float2(*(__half2*)&raw.x);
        float2 p1 = __half22float2(*(__half2*)&raw.y);
        float2 p2 = __half22float2(*(__half2*)&raw.z);
        float2 p3 = __half22float2(*(__half2*)&raw.w);
        s0 += p0.x; s1 += p0.y; s2 += p1.x; s3 += p1.y;
        s4 += p2.x; s5 += p2.y; s6 += p3.x; s7 += p3.y;
    }
    uint4 o;
    *(__half2*)&o.x = __floats2half2_rn(s0 * inv, s1 * inv);
    *(__half2*)&o.y = __floats2half2_rn(s2 * inv, s3 * inv);
    *(__half2*)&o.z = __floats2half2_rn(s4 * inv, s5 * inv);
    *(__half2*)&o.w = __floats2half2_rn(s6 * inv, s7 * inv);
    ((uint4*)g_MH)[(size_t)node * 8 + c] = o;
}

// ---------------- tf32 helpers ----------------------------------------------
__device__ __forceinline__ uint32_t f2tf32(float x) {
    uint32_t r;
    asm("cvt.rna.tf32.f32 %0, %1;" : "=r"(r) : "f"(x));
    return r;
}

// ---------------- dense update via tensor cores ------------------------------
// XBout = [meanh‖xb](NP x 128) @ Wc(128 x 64) + b   (all fp16 I/O, in-place
// safe: each block's x-side reads only its own 128 rows before its stores)
__global__ void __launch_bounds__(256)
k_dense_mma(const __half* __restrict__ MEANH, const __half* __restrict__ Xin,
            const float* __restrict__ Wl, const float* __restrict__ bvec,
            const float* __restrict__ Wr, __half* __restrict__ XBout,
            int do_relu) {
    __shared__ uint32_t Bs[128][72];
    __shared__ float bsh[64];

    int tid  = threadIdx.x;
    int base = blockIdx.x * 128;

    for (int i = tid; i < 128 * 64; i += 256) {
        int k = i & 127, j = i >> 7;
        float w = (k < 64) ? __ldg(&Wl[j * 64 + k]) : __ldg(&Wr[j * 64 + k - 64]);
        Bs[k][j] = f2tf32(w);
    }
    if (tid < 64) bsh[tid] = __ldg(&bvec[tid]);
    __syncthreads();

    int warp = tid >> 5, lane = tid & 31;
    int r = lane >> 2, c = lane & 3;
    int row0 = base + warp * 16 + r;        // rows row0, row0+8

    const __half* M0 = MEANH + (size_t)row0 * 64;
    const __half* M1 = MEANH + (size_t)(row0 + 8) * 64;
    const __half* X0 = Xin   + (size_t)row0 * 64;
    const __half* X1 = Xin   + (size_t)(row0 + 8) * 64;

    float acc[8][4];
#pragma unroll
    for (int nf = 0; nf < 8; ++nf)
#pragma unroll
        for (int i = 0; i < 4; ++i) acc[nf][i] = 0.0f;

#pragma unroll
    for (int ks = 0; ks < 16; ++ks) {
        int k0 = ks * 8;
        uint32_t a0, a1, a2, a3;
        if (ks < 8) {
            a0 = f2tf32(__half2float(__ldg(&M0[k0 + c])));
            a1 = f2tf32(__half2float(__ldg(&M1[k0 + c])));
            a2 = f2tf32(__half2float(__ldg(&M0[k0 + c + 4])));
            a3 = f2tf32(__half2float(__ldg(&M1[k0 + c + 4])));
        } else {
            int kk = k0 - 64;
            a0 = f2tf32(__half2float(__ldg(&X0[kk + c])));
            a1 = f2tf32(__half2float(__ldg(&X1[kk + c])));
            a2 = f2tf32(__half2float(__ldg(&X0[kk + c + 4])));
            a3 = f2tf32(__half2float(__ldg(&X1[kk + c + 4])));
        }
#pragma unroll
        for (int nf = 0; nf < 8; ++nf) {
            uint32_t b0 = Bs[k0 + c][8 * nf + r];
            uint32_t b1 = Bs[k0 + c + 4][8 * nf + r];
            asm volatile(
                "mma.sync.aligned.m16n8k8.row.col.f32.tf32.tf32.f32 "
                "{%0,%1,%2,%3}, {%4,%5,%6,%7}, {%8,%9}, {%0,%1,%2,%3};"
                : "+f"(acc[nf][0]), "+f"(acc[nf][1]),
                  "+f"(acc[nf][2]), "+f"(acc[nf][3])
                : "r"(a0), "r"(a1), "r"(a2), "r"(a3), "r"(b0), "r"(b1));
        }
    }

#pragma unroll
    for (int nf = 0; nf < 8; ++nf) {
        int col = 8 * nf + 2 * c;
        float o0 = acc[nf][0] + bsh[col];
        float o1 = acc[nf][1] + bsh[col + 1];
        float o2 = acc[nf][2] + bsh[col];
        float o3 = acc[nf][3] + bsh[col + 1];
        if (do_relu) {
            o0 = fmaxf(o0, 0.0f); o1 = fmaxf(o1, 0.0f);
            o2 = fmaxf(o2, 0.0f); o3 = fmaxf(o3, 0.0f);
        }
        *(__half2*)&XBout[(size_t)row0 * 64 + col] =
            __floats2half2_rn(o0, o1);
        *(__half2*)&XBout[(size_t)(row0 + 8) * 64 + col] =
            __floats2half2_rn(o2, o3);
    }
}

// ---------------- scoring (fp16 features) ------------------------------------
// out[e] = dot(XB[u[e]], XB[NU+m[e]]); 8 threads/edge (16B fp16 chunks)
__global__ void k_score(const void* __restrict__ eli,
                        float* __restrict__ out, int EL) {
    int t = blockIdx.x * blockDim.x + threadIdx.x;
    if (t >= EL * 8) return;
    int e = t >> 3, c = t & 7;
    int f = g_flag32[0];
    int u = get_idx(eli, e, f);
    int m = get_idx(eli, EL + e, f);
    uint4 ra = __ldg((const uint4*)(g_XB + (size_t)u * H) + c);
    uint4 rb = __ldg((const uint4*)(g_XB + (size_t)(NU + m) * H) + c);
    float2 a0 = __half22float2(*(__half2*)&ra.x);
    float2 a1 = __half22float2(*(__half2*)&ra.y);
    float2 a2 = __half22float2(*(__half2*)&ra.z);
    float2 a3 = __half22float2(*(__half2*)&ra.w);
    float2 b0 = __half22float2(*(__half2*)&rb.x);
    float2 b1 = __half22float2(*(__half2*)&rb.y);
    float2 b2 = __half22float2(*(__half2*)&rb.z);
    float2 b3 = __half22float2(*(__half2*)&rb.w);
    float p = a0.x * b0.x + a0.y * b0.y + a1.x * b1.x + a1.y * b1.y
            + a2.x * b2.x + a2.y * b2.y + a3.x * b3.x + a3.y * b3.y;
    p += __shfl_xor_sync(0xffffffffu, p, 4);
    p += __shfl_xor_sync(0xffffffffu, p, 2);
    p += __shfl_xor_sync(0xffffffffu, p, 1);
    if (c == 0) out[e] = p;
}

// ---------------- launch ----------------------------------------------------
extern "C" void kernel_launch(void* const* d_in, const int* in_sizes, int n_in,
                              void* d_out, int out_size) {
    const float* movie_x   = (const float*)d_in[0];
    const float* user_emb  = (const float*)d_in[1];
    const float* movie_emb = (const float*)d_in[2];
    const float* lin_W     = (const float*)d_in[3];
    const float* lin_b     = (const float*)d_in[4];
    const float* W1l = (const float*)d_in[5];
    const float* b1  = (const float*)d_in[6];
    const float* W1r = (const float*)d_in[7];
    const float* W2l = (const float*)d_in[8];
    const float* b2  = (const float*)d_in[9];
    const float* W2r = (const float*)d_in[10];
    const void*  ei  = d_in[11];
    const void*  eli = d_in[12];
    int E  = in_sizes[11] / 2;
    int EL = in_sizes[12] / 2;

    void *pCNT, *pXB, *pMH;
    cudaGetSymbolAddress(&pCNT, g_CNT);
    cudaGetSymbolAddress(&pXB, g_XB);
    cudaGetSymbolAddress(&pMH, g_MH);

    cudaMemsetAsync(pCNT, 0, (size_t)NP * sizeof(int), 0);

    k_detect<<<4, 256>>>((const long long*)ei, 1024);

    // fp16 features: users from input, movies via small GEMM
    k_conv_user<<<(NU * H / 2 + 255) / 256, 256>>>((const float2*)user_emb);
    k_init_movie<<<NM / 32, 512>>>(movie_x, lin_W, lin_b, movie_emb);

    // CSR build (shared by both layers)
    k_count<<<(E + 255) / 256, 256>>>(ei, E);
    k_inv<<<(NP + 255) / 256, 256>>>();
    k_blocksum<<<NB, 1024>>>();
    k_scan_bs<<<1, 512>>>();
    k_scan_local<<<NB, 1024>>>();
    k_place<<<(E + 255) / 256, 256>>>(ei, E);

    int ggrid = (NP * 8 + 255) / 256;

    // layer 1 (in-place on XB)
    k_gather_mean<<<ggrid, 256>>>();
    k_dense_mma<<<NP / 128, 256>>>((const __half*)pMH, (const __half*)pXB,
                                   W1l, b1, W1r, (__half*)pXB, 1);
    // layer 2 (in-place on XB)
    k_gather_mean<<<ggrid, 256>>>();
    k_dense_mma<<<NP / 128, 256>>>((const __half*)pMH, (const __half*)pXB,
                                   W2l, b2, W2r, (__half*)pXB, 0);

    // scoring from fp16 final features
    k_score<<<(EL * 8 + 255) / 256, 256>>>(eli, (float*)d_out, EL);
}